// round 14
// baseline (speedup 1.0000x reference)
#include <cuda_runtime.h>
#include <cstdint>

#define B    4096
#define S    200
#define E    300
#define TAGS 2
#define EV4  75          // float4 per embedding row

#define PCTA 512         // pool CTAs (8 rows each)
#define TCTA 120         // transpose CTAs (run concurrently)

#define GM   32          // rows per GEMM CTA
#define NT   128         // threads per GEMM CTA
#define NPAD 301         // conflict-free smem row stride (SCALAR access only)
#define NW   320         // padded N: 16 groups x 20

// device scratch
__device__ float g_pooled[B * E];
__device__ float g_w1t[E * NW];   // wt[k*NW+n] = w[n*E+k]; pads stay 0 (zero-init)
__device__ float g_w2t[E * NW];

typedef unsigned long long u64;
__device__ __forceinline__ u64 pack2(float x)
{ u64 r; asm("mov.b64 %0, {%1, %1};" : "=l"(r) : "f"(x)); return r; }
__device__ __forceinline__ u64 fma2(u64 a, u64 b, u64 c)
{ u64 d; asm("fma.rn.f32x2 %0, %1, %2, %3;" : "=l"(d) : "l"(a), "l"(b), "l"(c)); return d; }
__device__ __forceinline__ float lo32(u64 v) { return __uint_as_float((uint32_t)(v & 0xffffffffull)); }
__device__ __forceinline__ float hi32(u64 v) { return __uint_as_float((uint32_t)(v >> 32)); }
// 16B L2 read as two packed f32x2 operands (read-only path)
__device__ __forceinline__ void ldg2(const float* p, u64& x, u64& y)
{ asm("ld.global.nc.v2.u64 {%0, %1}, [%2];" : "=l"(x), "=l"(y) : "l"(p)); }

// ---------------------------------------------------------------------------
// Kernel 1: CTAs [0,512): gather+mean-pool, warp-per-row.
//           CTAs [512,512+120): transpose+pad W1,W2 (hidden under the gather).
// (unchanged — measured at the HBM random-row floor)
// ---------------------------------------------------------------------------
__global__ __launch_bounds__(256) void pool_and_prep(
    const int*   __restrict__ x,
    const float* __restrict__ emb,
    const float* __restrict__ w1,
    const float* __restrict__ w2)
{
    if (blockIdx.x >= PCTA) {
        const int total = E * E;
        const int start = (blockIdx.x - PCTA) * 256 + threadIdx.x;
        const int step  = TCTA * 256;
        for (int idx = start; idx < 2 * total; idx += step) {
            const int sel = idx / total;            // 0 -> w1, 1 -> w2
            const int e   = idx - sel * total;      // coalesced over n*E+k
            const int n = e / E, k = e % E;
            const float v = sel ? w2[e] : w1[e];
            if (sel) g_w2t[k * NW + n] = v;
            else     g_w1t[k * NW + n] = v;
        }
        return;
    }

    __shared__ int s_ids[8 * S];
    const int b0 = blockIdx.x * 8;
    {
        const int4* src = (const int4*)(x + b0 * S);
        int4* dst = (int4*)s_ids;
#pragma unroll
        for (int i = 0; i < 2; ++i) {
            const int idx = threadIdx.x + i * 256;
            if (idx < 8 * S / 4) dst[idx] = src[idx];
        }
    }
    __syncthreads();

    const int w = threadIdx.x >> 5, lane = threadIdx.x & 31;
    const bool has2 = lane < (EV4 - 64);            // lanes 0..10 own slot lane+64
    const float4* __restrict__ ev = (const float4*)emb;
    const int* __restrict__ rid = s_ids + w * S;

    float4 a0 = {0,0,0,0}, a1 = {0,0,0,0}, a2 = {0,0,0,0};
#pragma unroll 4
    for (int t = 0; t < S; ++t) {
        const int base = rid[t] * EV4;              // <= 37.5M, fits int32
        float4 v0 = __ldg(ev + base + lane);
        float4 v1 = __ldg(ev + base + lane + 32);
        a0.x += v0.x; a0.y += v0.y; a0.z += v0.z; a0.w += v0.w;
        a1.x += v1.x; a1.y += v1.y; a1.z += v1.z; a1.w += v1.w;
        if (has2) {
            float4 v2 = __ldg(ev + base + lane + 64);
            a2.x += v2.x; a2.y += v2.y; a2.z += v2.z; a2.w += v2.w;
        }
    }
    const float sc = 1.0f / (float)S;
    float4* p = (float4*)(g_pooled + (b0 + w) * E);
    p[lane]      = make_float4(a0.x*sc, a0.y*sc, a0.z*sc, a0.w*sc);
    p[lane + 32] = make_float4(a1.x*sc, a1.y*sc, a1.z*sc, a1.w*sc);
    if (has2)
        p[lane + 64] = make_float4(a2.x*sc, a2.y*sc, a2.z*sc, a2.w*sc);
}

// ---------------------------------------------------------------------------
// One layer, BARRIER-FREE: W streamed straight from L2 (ld.global.nc),
// 4 rows x 20 cols per thread, 40 independent f32x2 chains hide L2 latency.
// ---------------------------------------------------------------------------
__device__ __forceinline__ void gemmL2(
    const float* __restrict__ Wt,
    const float* __restrict__ s_a,
    int r0, int n0, u64 acc2[40])
{
#pragma unroll
    for (int j = 0; j < 40; ++j) acc2[j] = 0ull;

    const float* __restrict__ wp = Wt + n0;   // row k at wp + k*NW

#pragma unroll 5
    for (int k = 0; k < E; ++k) {
        // 5 x 16B independent L2 loads (this k's 20 cols)
        u64 w0, w1, w2, w3, w4, w5, w6, w7, w8, w9;
        const float* row = wp + k * NW;
        ldg2(row,      w0, w1);
        ldg2(row + 4,  w2, w3);
        ldg2(row + 8,  w4, w5);
        ldg2(row + 12, w6, w7);
        ldg2(row + 16, w8, w9);

        u64 a[4];
#pragma unroll
        for (int r = 0; r < 4; ++r)
            a[r] = pack2(s_a[(r0 + r) * NPAD + k]);   // scalar LDS, bank-clean

#pragma unroll
        for (int r = 0; r < 4; ++r) {
            acc2[r*10 + 0] = fma2(a[r], w0, acc2[r*10 + 0]);
            acc2[r*10 + 1] = fma2(a[r], w1, acc2[r*10 + 1]);
            acc2[r*10 + 2] = fma2(a[r], w2, acc2[r*10 + 2]);
            acc2[r*10 + 3] = fma2(a[r], w3, acc2[r*10 + 3]);
            acc2[r*10 + 4] = fma2(a[r], w4, acc2[r*10 + 4]);
            acc2[r*10 + 5] = fma2(a[r], w5, acc2[r*10 + 5]);
            acc2[r*10 + 6] = fma2(a[r], w6, acc2[r*10 + 6]);
            acc2[r*10 + 7] = fma2(a[r], w7, acc2[r*10 + 7]);
            acc2[r*10 + 8] = fma2(a[r], w8, acc2[r*10 + 8]);
            acc2[r*10 + 9] = fma2(a[r], w9, acc2[r*10 + 9]);
        }
    }
}

// ---------------------------------------------------------------------------
// Kernel 2: 32 rows/CTA, 128 threads, grid 128, 4 rows x 20 cols per thread.
// Only 3 block-wide syncs total (staging, h1 handoff x2, partials).
// ---------------------------------------------------------------------------
__global__ __launch_bounds__(NT) void gemm_head(
    const float* __restrict__ pooled,
    const float* __restrict__ w3,
    float*       __restrict__ out)
{
    __shared__ float s_a[GM * NPAD];        // 38528 B
    __shared__ float s_w3[TAGS * NW];       //  2560 B
    __shared__ float s_part[GM * 16 * 2];   //  4096 B  (45184 total, static)

    const int tid = threadIdx.x;
    const int b0  = blockIdx.x * GM;

    // stage pooled rows (vector gmem load, SCALAR smem stores) + padded w3
    {
        const float4* src = (const float4*)(pooled + b0 * E);
#pragma unroll
        for (int i = 0; i < 19; ++i) {
            const int idx = tid + i * NT;        // 0..2399 float4
            if (idx < GM * E / 4) {
                const int m = idx / EV4, s = idx - m * EV4;
                const float4 v = src[idx];
                float* dst = &s_a[m * NPAD + s * 4];
                dst[0] = v.x; dst[1] = v.y; dst[2] = v.z; dst[3] = v.w;
            }
        }
#pragma unroll
        for (int i = 0; i < 5; ++i) {
            const int idx = tid + i * NT;
            if (idx < TAGS * NW) {
                const int t = idx / NW, n = idx % NW;
                s_w3[idx] = (n < E) ? w3[t * E + n] : 0.0f;
            }
        }
    }
    __syncthreads();

    const int r0 = (tid & 7) * 4;       // rows r0..r0+3
    const int g  = tid >> 3;            // 0..15
    const int n0 = g * 20;

    u64 acc2[40];

    // layer 1 (barrier-free)
    gemmL2(g_w1t, s_a, r0, n0, acc2);
    __syncthreads();                    // all layer-1 reads of s_a complete
#pragma unroll
    for (int r = 0; r < 4; ++r) {
#pragma unroll
        for (int j = 0; j < 10; ++j) {
            const int n = n0 + 2 * j;
            const u64 v = acc2[r * 10 + j];
            if (n     < E) s_a[(r0 + r) * NPAD + n]     = fmaxf(lo32(v), 0.0f);
            if (n + 1 < E) s_a[(r0 + r) * NPAD + n + 1] = fmaxf(hi32(v), 0.0f);
        }
    }
    __syncthreads();                    // h1 visible

    // layer 2 (barrier-free) + fused head
    gemmL2(g_w2t, s_a, r0, n0, acc2);

#pragma unroll
    for (int r = 0; r < 4; ++r) {
        float s0 = 0.0f, s1 = 0.0f;
#pragma unroll
        for (int j = 0; j < 10; ++j) {
            const u64 v = acc2[r * 10 + j];
            const float lo = fmaxf(lo32(v), 0.0f);      // pad cols: w=0 -> acc=0
            const float hi = fmaxf(hi32(v), 0.0f);
            s0 = fmaf(lo, s_w3[n0 + 2*j],          s0);
            s0 = fmaf(hi, s_w3[n0 + 2*j + 1],      s0);
            s1 = fmaf(lo, s_w3[NW + n0 + 2*j],     s1);
            s1 = fmaf(hi, s_w3[NW + n0 + 2*j + 1], s1);
        }
        s_part[((r0 + r) * 16 + g) * 2 + 0] = s0;
        s_part[((r0 + r) * 16 + g) * 2 + 1] = s1;
    }
    __syncthreads();

    if (tid < GM * TAGS) {
        const int mm = tid >> 1, t = tid & 1;
        float s = 0.0f;
#pragma unroll
        for (int gg = 0; gg < 16; ++gg)
            s += s_part[(mm * 16 + gg) * 2 + t];
        out[(b0 + mm) * TAGS + t] = s;
    }
}

// ---------------------------------------------------------------------------
// Launch
// ---------------------------------------------------------------------------
extern "C" void kernel_launch(void* const* d_in, const int* in_sizes, int n_in,
                              void* d_out, int out_size)
{
    const int*   x   = (const int*)d_in[0];
    const float* emb = (const float*)d_in[1];
    const float* w1  = (const float*)d_in[2];
    const float* w2  = (const float*)d_in[3];
    const float* w3  = (const float*)d_in[4];
    float* out = (float*)d_out;

    float* pooled; cudaGetSymbolAddress((void**)&pooled, g_pooled);

    pool_and_prep<<<PCTA + TCTA, 256>>>(x, emb, w1, w2);
    gemm_head<<<B / GM, NT>>>(pooled, w3, out);
}

// round 15
// speedup vs baseline: 1.7116x; 1.7116x over previous
#include <cuda_runtime.h>
#include <cstdint>

#define B    4096
#define S    200
#define E    300
#define TAGS 2
#define EV4  75          // float4 per embedding row

#define PCTA 512         // pool CTAs (8 rows each)
#define TCTA 120         // transpose CTAs (run concurrently)

#define GM   32          // rows per GEMM CTA
#define NT   256         // threads per GEMM CTA (8 warps: 2 per SMSP)
#define NPAD 301         // conflict-free smem row stride (SCALAR access only)
#define NW   320         // padded N: 16 groups x 20
#define BK   20
#define NKT  15          // 300/20
#define TILE_F  (BK * NW)        // 6400 floats per tile
#define TILE_F4 (TILE_F / 4)     // 1600 float4

// dynamic smem layout (floats)
#define OFF_A    (2 * TILE_F)                 // 12800
#define OFF_W3   (OFF_A + GM * NPAD)          // 22432
#define OFF_PART (OFF_W3 + TAGS * NW)         // 23072
#define SMEM_FLOATS (OFF_PART + GM * 16 * 2)  // 24096
#define SMEM_BYTES  (SMEM_FLOATS * 4)         // 96384 B

// device scratch
__device__ float g_pooled[B * E];
__device__ float g_w1t[E * NW];   // wt[k*NW+n] = w[n*E+k]; pads stay 0 (zero-init)
__device__ float g_w2t[E * NW];

// ---------------- PTX helpers ----------------
__device__ __forceinline__ void cp16(uint32_t saddr, const void* g)
{ asm volatile("cp.async.cg.shared.global [%0], [%1], 16;" :: "r"(saddr), "l"(g)); }
__device__ __forceinline__ void cp_commit()
{ asm volatile("cp.async.commit_group;"); }

typedef unsigned long long u64;
__device__ __forceinline__ u64 pack2(float x)
{ u64 r; asm("mov.b64 %0, {%1, %1};" : "=l"(r) : "f"(x)); return r; }
__device__ __forceinline__ u64 fma2(u64 a, u64 b, u64 c)
{ u64 d; asm("fma.rn.f32x2 %0, %1, %2, %3;" : "=l"(d) : "l"(a), "l"(b), "l"(c)); return d; }
__device__ __forceinline__ float lo32(u64 v) { return __uint_as_float((uint32_t)(v & 0xffffffffull)); }
__device__ __forceinline__ float hi32(u64 v) { return __uint_as_float((uint32_t)(v >> 32)); }

// ---------------------------------------------------------------------------
// Kernel 1: CTAs [0,512): gather+mean-pool, warp-per-row.
//           CTAs [512,512+120): transpose+pad W1,W2 (hidden under the gather).
// (unchanged — measured at the HBM random-row floor)
// ---------------------------------------------------------------------------
__global__ __launch_bounds__(256) void pool_and_prep(
    const int*   __restrict__ x,
    const float* __restrict__ emb,
    const float* __restrict__ w1,
    const float* __restrict__ w2)
{
    if (blockIdx.x >= PCTA) {
        const int total = E * E;
        const int start = (blockIdx.x - PCTA) * 256 + threadIdx.x;
        const int step  = TCTA * 256;
        for (int idx = start; idx < 2 * total; idx += step) {
            const int sel = idx / total;            // 0 -> w1, 1 -> w2
            const int e   = idx - sel * total;      // coalesced over n*E+k
            const int n = e / E, k = e % E;
            const float v = sel ? w2[e] : w1[e];
            if (sel) g_w2t[k * NW + n] = v;
            else     g_w1t[k * NW + n] = v;
        }
        return;
    }

    __shared__ int s_ids[8 * S];
    const int b0 = blockIdx.x * 8;
    {
        const int4* src = (const int4*)(x + b0 * S);
        int4* dst = (int4*)s_ids;
#pragma unroll
        for (int i = 0; i < 2; ++i) {
            const int idx = threadIdx.x + i * 256;
            if (idx < 8 * S / 4) dst[idx] = src[idx];
        }
    }
    __syncthreads();

    const int w = threadIdx.x >> 5, lane = threadIdx.x & 31;
    const bool has2 = lane < (EV4 - 64);            // lanes 0..10 own slot lane+64
    const float4* __restrict__ ev = (const float4*)emb;
    const int* __restrict__ rid = s_ids + w * S;

    float4 a0 = {0,0,0,0}, a1 = {0,0,0,0}, a2 = {0,0,0,0};
#pragma unroll 4
    for (int t = 0; t < S; ++t) {
        const int base = rid[t] * EV4;              // <= 37.5M, fits int32
        float4 v0 = __ldg(ev + base + lane);
        float4 v1 = __ldg(ev + base + lane + 32);
        a0.x += v0.x; a0.y += v0.y; a0.z += v0.z; a0.w += v0.w;
        a1.x += v1.x; a1.y += v1.y; a1.z += v1.z; a1.w += v1.w;
        if (has2) {
            float4 v2 = __ldg(ev + base + lane + 64);
            a2.x += v2.x; a2.y += v2.y; a2.z += v2.z; a2.w += v2.w;
        }
    }
    const float sc = 1.0f / (float)S;
    float4* p = (float4*)(g_pooled + (b0 + w) * E);
    p[lane]      = make_float4(a0.x*sc, a0.y*sc, a0.z*sc, a0.w*sc);
    p[lane + 32] = make_float4(a1.x*sc, a1.y*sc, a1.z*sc, a1.w*sc);
    if (has2)
        p[lane + 64] = make_float4(a2.x*sc, a2.y*sc, a2.z*sc, a2.w*sc);
}

// ---------------------------------------------------------------------------
// One layer, 2 rows x 20 cols per thread. PROVEN 2-sync double buffer, BK=20.
// All NT threads must call (uniform).
// ---------------------------------------------------------------------------
__device__ __forceinline__ void gemmT(
    const float* __restrict__ Wt,
    const float* __restrict__ s_a,
    float* __restrict__ s_w,            // 2 tiles, 16B-aligned base
    int r0, int n0, int tid, u64 acc2[20])
{
#pragma unroll
    for (int j = 0; j < 20; ++j) acc2[j] = 0ull;

    const uint32_t sb0 = (uint32_t)__cvta_generic_to_shared(s_w);
    const uint32_t sb1 = sb0 + TILE_F * 4;

    // prologue: tile 0 -> buf 0
#pragma unroll
    for (int i = 0; i < 7; ++i) {
        const int idx = tid + i * NT;
        if (idx < TILE_F4) cp16(sb0 + idx * 16, Wt + idx * 4);
    }
    cp_commit();

    for (int kt = 0; kt < NKT; ++kt) {
        if (kt + 1 < NKT) {
            const uint32_t dst = ((kt + 1) & 1) ? sb1 : sb0;
            const float* src = Wt + (kt + 1) * TILE_F;
#pragma unroll
            for (int i = 0; i < 7; ++i) {
                const int idx = tid + i * NT;
                if (idx < TILE_F4) cp16(dst + idx * 16, src + idx * 4);
            }
            cp_commit();
            asm volatile("cp.async.wait_group 1;");   // my tile-kt copies done
        } else {
            asm volatile("cp.async.wait_group 0;");
        }
        __syncthreads();              // ALL threads' tile-kt copies visible

        const float* wb = s_w + (kt & 1) * TILE_F;
        const int kb = kt * BK;
#pragma unroll
        for (int kk = 0; kk < BK; ++kk) {
            const u64 a0 = pack2(s_a[r0 * NPAD + kb + kk]);        // scalar LDS
            const u64 a1 = pack2(s_a[(r0 + 1) * NPAD + kb + kk]);
            // offset (kk*NW + n0) floats = kk*1280 + 80g bytes -> 16B aligned
            const ulonglong2* wr = (const ulonglong2*)(wb + kk * NW + n0);
#pragma unroll
            for (int j = 0; j < 5; ++j) {
                const ulonglong2 wv = wr[j];
                acc2[2*j + 0]      = fma2(a0, wv.x, acc2[2*j + 0]);
                acc2[2*j + 1]      = fma2(a0, wv.y, acc2[2*j + 1]);
                acc2[10 + 2*j + 0] = fma2(a1, wv.x, acc2[10 + 2*j + 0]);
                acc2[10 + 2*j + 1] = fma2(a1, wv.y, acc2[10 + 2*j + 1]);
            }
        }
        __syncthreads();              // buf kt free before next refill
    }
}

// ---------------------------------------------------------------------------
// Kernel 2: 32 rows/CTA, 256 threads (2 warps per SMSP -> stall coverage),
// grid 128, 2 rows x 20 cols per thread:
//   relu(relu(pooled W1^T) W2^T) W3^T -> out
// ---------------------------------------------------------------------------
__global__ __launch_bounds__(NT) void gemm_head(
    const float* __restrict__ pooled,
    const float* __restrict__ w3,
    float*       __restrict__ out)
{
    extern __shared__ float smem[];
    float* s_w    = smem;               // 2 tiles
    float* s_a    = smem + OFF_A;
    float* s_w3   = smem + OFF_W3;
    float* s_part = smem + OFF_PART;

    const int tid = threadIdx.x;
    const int b0  = blockIdx.x * GM;

    // stage pooled rows (vector gmem load, SCALAR smem stores: NPAD rows only
    // 4B-aligned) + padded w3
    {
        const float4* src = (const float4*)(pooled + b0 * E);
#pragma unroll
        for (int i = 0; i < 10; ++i) {
            const int idx = tid + i * NT;        // 0..2399 float4
            if (idx < GM * E / 4) {
                const int m = idx / EV4, s = idx - m * EV4;
                const float4 v = src[idx];
                float* dst = &s_a[m * NPAD + s * 4];
                dst[0] = v.x; dst[1] = v.y; dst[2] = v.z; dst[3] = v.w;
            }
        }
#pragma unroll
        for (int i = 0; i < 3; ++i) {
            const int idx = tid + i * NT;
            if (idx < TAGS * NW) {
                const int t = idx / NW, n = idx % NW;
                s_w3[idx] = (n < E) ? w3[t * E + n] : 0.0f;
            }
        }
    }
    // first __syncthreads inside gemmT (post-wait) fences the staging stores

    const int r0 = (tid & 15) * 2;      // rows r0, r0+1
    const int g  = tid >> 4;            // 0..15
    const int n0 = g * 20;

    u64 acc2[20];

    // layer 1
    gemmT(g_w1t, s_a, s_w, r0, n0, tid, acc2);
    // gemmT ends with __syncthreads: all layer-1 reads of s_a complete
#pragma unroll
    for (int r = 0; r < 2; ++r) {
#pragma unroll
        for (int j = 0; j < 10; ++j) {
            const int n = n0 + 2 * j;
            const u64 v = acc2[r * 10 + j];
            if (n     < E) s_a[(r0 + r) * NPAD + n]     = fmaxf(lo32(v), 0.0f);
            if (n + 1 < E) s_a[(r0 + r) * NPAD + n + 1] = fmaxf(hi32(v), 0.0f);
        }
    }
    // layer 2 (+fused head); first post-wait sync inside orders the h1 stores
    gemmT(g_w2t, s_a, s_w, r0, n0, tid, acc2);

#pragma unroll
    for (int r = 0; r < 2; ++r) {
        float s0 = 0.0f, s1 = 0.0f;
#pragma unroll
        for (int j = 0; j < 10; ++j) {
            const u64 v = acc2[r * 10 + j];
            const float lo = fmaxf(lo32(v), 0.0f);      // pad cols: w=0 -> acc=0
            const float hi = fmaxf(hi32(v), 0.0f);
            s0 = fmaf(lo, s_w3[n0 + 2*j],          s0);
            s0 = fmaf(hi, s_w3[n0 + 2*j + 1],      s0);
            s1 = fmaf(lo, s_w3[NW + n0 + 2*j],     s1);
            s1 = fmaf(hi, s_w3[NW + n0 + 2*j + 1], s1);
        }
        s_part[((r0 + r) * 16 + g) * 2 + 0] = s0;
        s_part[((r0 + r) * 16 + g) * 2 + 1] = s1;
    }
    __syncthreads();

    if (tid < GM * TAGS) {
        const int mm = tid >> 1, t = tid & 1;
        float s = 0.0f;
#pragma unroll
        for (int gg = 0; gg < 16; ++gg)
            s += s_part[(mm * 16 + gg) * 2 + t];
        out[(b0 + mm) * TAGS + t] = s;
    }
}

// ---------------------------------------------------------------------------
// Launch
// ---------------------------------------------------------------------------
extern "C" void kernel_launch(void* const* d_in, const int* in_sizes, int n_in,
                              void* d_out, int out_size)
{
    const int*   x   = (const int*)d_in[0];
    const float* emb = (const float*)d_in[1];
    const float* w1  = (const float*)d_in[2];
    const float* w2  = (const float*)d_in[3];
    const float* w3  = (const float*)d_in[4];
    float* out = (float*)d_out;

    float* pooled; cudaGetSymbolAddress((void**)&pooled, g_pooled);

    cudaFuncSetAttribute(gemm_head,
                         cudaFuncAttributeMaxDynamicSharedMemorySize, SMEM_BYTES);

    pool_and_prep<<<PCTA + TCTA, 256>>>(x, emb, w1, w2);
    gemm_head<<<B / GM, NT, SMEM_BYTES>>>(pooled, w3, out);
}

// round 16
// speedup vs baseline: 1.7119x; 1.0002x over previous
#include <cuda_runtime.h>
#include <cstdint>

#define B    4096
#define S    200
#define E    300
#define TAGS 2
#define EV4  75          // float4 per embedding row

#define PCTA 512         // pool CTAs (8 rows each)
#define TCTA 120         // transpose CTAs (run concurrently)

#define GM    32         // rows per GEMM CTA
#define NT    256        // threads per GEMM CTA
#define NPADT 36         // s_aT row stride (floats): 144B -> 16B aligned, bank-rotating
#define NW    320        // padded N: 32 groups x 10
#define BK    20
#define NKT   15         // 300/20
#define TILE_F  (BK * NW)        // 6400 floats per tile
#define TILE_F4 (TILE_F / 4)     // 1600 float4

// dynamic smem layout (floats)
#define OFF_AT   (2 * TILE_F)                  // 12800
#define OFF_W3   (OFF_AT + E * NPADT)          // 23600
#define OFF_PART (OFF_W3 + TAGS * NW)          // 24240
#define SMEM_FLOATS (OFF_PART + GM * 32 * 2)   // 26288
#define SMEM_BYTES  (SMEM_FLOATS * 4)          // 105152 B

// device scratch
__device__ float g_pooled[B * E];
__device__ float g_w1t[E * NW];   // wt[k*NW+n] = w[n*E+k]; pads stay 0 (zero-init)
__device__ float g_w2t[E * NW];

// ---------------- PTX helpers ----------------
__device__ __forceinline__ void cp16(uint32_t saddr, const void* g)
{ asm volatile("cp.async.cg.shared.global [%0], [%1], 16;" :: "r"(saddr), "l"(g)); }
__device__ __forceinline__ void cp_commit()
{ asm volatile("cp.async.commit_group;"); }

typedef unsigned long long u64;
__device__ __forceinline__ u64 pack2(float x)
{ u64 r; asm("mov.b64 %0, {%1, %1};" : "=l"(r) : "f"(x)); return r; }
__device__ __forceinline__ u64 fma2(u64 a, u64 b, u64 c)
{ u64 d; asm("fma.rn.f32x2 %0, %1, %2, %3;" : "=l"(d) : "l"(a), "l"(b), "l"(c)); return d; }
__device__ __forceinline__ float lo32(u64 v) { return __uint_as_float((uint32_t)(v & 0xffffffffull)); }
__device__ __forceinline__ float hi32(u64 v) { return __uint_as_float((uint32_t)(v >> 32)); }

// ---------------------------------------------------------------------------
// Kernel 1: CTAs [0,512): gather+mean-pool, warp-per-row.
//           CTAs [512,512+120): transpose+pad W1,W2 (hidden under the gather).
// (unchanged — measured at the HBM random-row floor)
// ---------------------------------------------------------------------------
__global__ __launch_bounds__(256) void pool_and_prep(
    const int*   __restrict__ x,
    const float* __restrict__ emb,
    const float* __restrict__ w1,
    const float* __restrict__ w2)
{
    if (blockIdx.x >= PCTA) {
        const int total = E * E;
        const int start = (blockIdx.x - PCTA) * 256 + threadIdx.x;
        const int step  = TCTA * 256;
        for (int idx = start; idx < 2 * total; idx += step) {
            const int sel = idx / total;            // 0 -> w1, 1 -> w2
            const int e   = idx - sel * total;      // coalesced over n*E+k
            const int n = e / E, k = e % E;
            const float v = sel ? w2[e] : w1[e];
            if (sel) g_w2t[k * NW + n] = v;
            else     g_w1t[k * NW + n] = v;
        }
        return;
    }

    __shared__ int s_ids[8 * S];
    const int b0 = blockIdx.x * 8;
    {
        const int4* src = (const int4*)(x + b0 * S);
        int4* dst = (int4*)s_ids;
#pragma unroll
        for (int i = 0; i < 2; ++i) {
            const int idx = threadIdx.x + i * 256;
            if (idx < 8 * S / 4) dst[idx] = src[idx];
        }
    }
    __syncthreads();

    const int w = threadIdx.x >> 5, lane = threadIdx.x & 31;
    const bool has2 = lane < (EV4 - 64);            // lanes 0..10 own slot lane+64
    const float4* __restrict__ ev = (const float4*)emb;
    const int* __restrict__ rid = s_ids + w * S;

    float4 a0 = {0,0,0,0}, a1 = {0,0,0,0}, a2 = {0,0,0,0};
#pragma unroll 4
    for (int t = 0; t < S; ++t) {
        const int base = rid[t] * EV4;              // <= 37.5M, fits int32
        float4 v0 = __ldg(ev + base + lane);
        float4 v1 = __ldg(ev + base + lane + 32);
        a0.x += v0.x; a0.y += v0.y; a0.z += v0.z; a0.w += v0.w;
        a1.x += v1.x; a1.y += v1.y; a1.z += v1.z; a1.w += v1.w;
        if (has2) {
            float4 v2 = __ldg(ev + base + lane + 64);
            a2.x += v2.x; a2.y += v2.y; a2.z += v2.z; a2.w += v2.w;
        }
    }
    const float sc = 1.0f / (float)S;
    float4* p = (float4*)(g_pooled + (b0 + w) * E);
    p[lane]      = make_float4(a0.x*sc, a0.y*sc, a0.z*sc, a0.w*sc);
    p[lane + 32] = make_float4(a1.x*sc, a1.y*sc, a1.z*sc, a1.w*sc);
    if (has2)
        p[lane + 64] = make_float4(a2.x*sc, a2.y*sc, a2.z*sc, a2.w*sc);
}

// ---------------------------------------------------------------------------
// One layer, 4 rows x 10 cols per thread, A transposed in smem (s_aT[k][m]):
//   a-read: 1x LDS.128 of DISTINCT data (4 wf), w-read: 5x LDS.64 (10 wf)
//   -> 14 wavefronts per 20 FMA2 (was 22).
// PROVEN 2-sync double buffer, BK=20. All NT threads must call (uniform).
// ---------------------------------------------------------------------------
__device__ __forceinline__ void gemmT(
    const float* __restrict__ Wt,
    const float* __restrict__ s_aT,
    float* __restrict__ s_w,            // 2 tiles, 16B-aligned base
    int m0, int n0, int tid, u64 acc2[20])
{
#pragma unroll
    for (int j = 0; j < 20; ++j) acc2[j] = 0ull;

    const uint32_t sb0 = (uint32_t)__cvta_generic_to_shared(s_w);
    const uint32_t sb1 = sb0 + TILE_F * 4;

    // prologue: tile 0 -> buf 0
#pragma unroll
    for (int i = 0; i < 7; ++i) {
        const int idx = tid + i * NT;
        if (idx < TILE_F4) cp16(sb0 + idx * 16, Wt + idx * 4);
    }
    cp_commit();

    for (int kt = 0; kt < NKT; ++kt) {
        if (kt + 1 < NKT) {
            const uint32_t dst = ((kt + 1) & 1) ? sb1 : sb0;
            const float* src = Wt + (kt + 1) * TILE_F;
#pragma unroll
            for (int i = 0; i < 7; ++i) {
                const int idx = tid + i * NT;
                if (idx < TILE_F4) cp16(dst + idx * 16, src + idx * 4);
            }
            cp_commit();
            asm volatile("cp.async.wait_group 1;");   // my tile-kt copies done
        } else {
            asm volatile("cp.async.wait_group 0;");
        }
        __syncthreads();              // ALL threads' tile-kt copies visible

        const float* wb = s_w + (kt & 1) * TILE_F;
        const int kb = kt * BK;
#pragma unroll
        for (int kk = 0; kk < BK; ++kk) {
            // 4 rows of A for this k: one 16B distinct-data LDS.128
            const float4 av = *(const float4*)&s_aT[(kb + kk) * NPADT + m0];
            const u64 a0 = pack2(av.x), a1 = pack2(av.y);
            const u64 a2 = pack2(av.z), a3 = pack2(av.w);
            // 5 col-pairs: 8B-aligned LDS.64 each (offset kk*1280 + g*40 bytes)
            const u64* wr = (const u64*)(wb + kk * NW + n0);
            const u64 w0 = wr[0], w1 = wr[1], w2 = wr[2], w3 = wr[3], w4 = wr[4];

            acc2[0]  = fma2(a0, w0, acc2[0]);  acc2[1]  = fma2(a0, w1, acc2[1]);
            acc2[2]  = fma2(a0, w2, acc2[2]);  acc2[3]  = fma2(a0, w3, acc2[3]);
            acc2[4]  = fma2(a0, w4, acc2[4]);
            acc2[5]  = fma2(a1, w0, acc2[5]);  acc2[6]  = fma2(a1, w1, acc2[6]);
            acc2[7]  = fma2(a1, w2, acc2[7]);  acc2[8]  = fma2(a1, w3, acc2[8]);
            acc2[9]  = fma2(a1, w4, acc2[9]);
            acc2[10] = fma2(a2, w0, acc2[10]); acc2[11] = fma2(a2, w1, acc2[11]);
            acc2[12] = fma2(a2, w2, acc2[12]); acc2[13] = fma2(a2, w3, acc2[13]);
            acc2[14] = fma2(a2, w4, acc2[14]);
            acc2[15] = fma2(a3, w0, acc2[15]); acc2[16] = fma2(a3, w1, acc2[16]);
            acc2[17] = fma2(a3, w2, acc2[17]); acc2[18] = fma2(a3, w3, acc2[18]);
            acc2[19] = fma2(a3, w4, acc2[19]);
        }
        __syncthreads();              // buf kt free before next refill
    }
}

// ---------------------------------------------------------------------------
// Kernel 2: 32 rows/CTA, 256 threads, grid 128, 4 rows x 10 cols per thread:
//   relu(relu(pooled W1^T) W2^T) W3^T -> out
// ---------------------------------------------------------------------------
__global__ __launch_bounds__(NT) void gemm_head(
    const float* __restrict__ pooled,
    const float* __restrict__ w3,
    float*       __restrict__ out)
{
    extern __shared__ float smem[];
    float* s_w    = smem;               // 2 tiles
    float* s_aT   = smem + OFF_AT;      // [300][36] transposed activations
    float* s_w3   = smem + OFF_W3;
    float* s_part = smem + OFF_PART;

    const int tid = threadIdx.x;
    const int b0  = blockIdx.x * GM;

    // stage pooled rows TRANSPOSED: s_aT[k][m] = pooled[b0+m][k]
    {
        const float4* src = (const float4*)(pooled + b0 * E);
#pragma unroll
        for (int i = 0; i < 10; ++i) {
            const int idx = tid + i * NT;        // 0..2399 float4
            if (idx < GM * E / 4) {
                const int m = idx / EV4, s = idx - m * EV4;
                const float4 v = src[idx];
                s_aT[(4 * s + 0) * NPADT + m] = v.x;
                s_aT[(4 * s + 1) * NPADT + m] = v.y;
                s_aT[(4 * s + 2) * NPADT + m] = v.z;
                s_aT[(4 * s + 3) * NPADT + m] = v.w;
            }
        }
#pragma unroll
        for (int i = 0; i < 3; ++i) {
            const int idx = tid + i * NT;
            if (idx < TAGS * NW) {
                const int t = idx / NW, n = idx % NW;
                s_w3[idx] = (n < E) ? w3[t * E + n] : 0.0f;
            }
        }
    }
    // first __syncthreads inside gemmT (post-wait) fences the staging stores

    const int m0 = (tid & 7) * 4;       // rows m0..m0+3
    const int g  = tid >> 3;            // 0..31
    const int n0 = g * 10;              // cols n0..n0+9

    u64 acc2[20];                       // [row r][col pair j] = acc2[r*5+j]

    // layer 1
    gemmT(g_w1t, s_aT, s_w, m0, n0, tid, acc2);
    // gemmT ends with __syncthreads: all layer-1 reads of s_aT complete
    // relu + transposed writeback: s_aT[n][m0..m0+3] as one STS.128 per n
#pragma unroll
    for (int j2 = 0; j2 < 10; ++j2) {
        const int n = n0 + j2;
        if (n < E) {
            const int jp = j2 >> 1;
            float4 v;
            if (j2 & 1) {
                v.x = fmaxf(hi32(acc2[0*5 + jp]), 0.0f);
                v.y = fmaxf(hi32(acc2[1*5 + jp]), 0.0f);
                v.z = fmaxf(hi32(acc2[2*5 + jp]), 0.0f);
                v.w = fmaxf(hi32(acc2[3*5 + jp]), 0.0f);
            } else {
                v.x = fmaxf(lo32(acc2[0*5 + jp]), 0.0f);
                v.y = fmaxf(lo32(acc2[1*5 + jp]), 0.0f);
                v.z = fmaxf(lo32(acc2[2*5 + jp]), 0.0f);
                v.w = fmaxf(lo32(acc2[3*5 + jp]), 0.0f);
            }
            *(float4*)&s_aT[n * NPADT + m0] = v;   // 16B aligned (NPADT=36, m0%4==0)
        }
    }
    // layer 2 (+fused head); first post-wait sync inside orders the h1 stores
    gemmT(g_w2t, s_aT, s_w, m0, n0, tid, acc2);

#pragma unroll
    for (int r = 0; r < 4; ++r) {
        float s0 = 0.0f, s1 = 0.0f;
#pragma unroll
        for (int j = 0; j < 5; ++j) {
            const u64 v = acc2[r * 5 + j];
            const float lo = fmaxf(lo32(v), 0.0f);      // pad cols: w=0 -> acc=0
            const float hi = fmaxf(hi32(v), 0.0f);
            s0 = fmaf(lo, s_w3[n0 + 2*j],          s0);
            s0 = fmaf(hi, s_w3[n0 + 2*j + 1],      s0);
            s1 = fmaf(lo, s_w3[NW + n0 + 2*j],     s1);
            s1 = fmaf(hi, s_w3[NW + n0 + 2*j + 1], s1);
        }
        s_part[((m0 + r) * 32 + g) * 2 + 0] = s0;
        s_part[((m0 + r) * 32 + g) * 2 + 1] = s1;
    }
    __syncthreads();

    if (tid < GM * TAGS) {
        const int mm = tid >> 1, t = tid & 1;
        float s = 0.0f;
#pragma unroll
        for (int gg = 0; gg < 32; ++gg)
            s += s_part[(mm * 32 + gg) * 2 + t];
        out[(b0 + mm) * TAGS + t] = s;
    }
}

// ---------------------------------------------------------------------------
// Launch
// ---------------------------------------------------------------------------
extern "C" void kernel_launch(void* const* d_in, const int* in_sizes, int n_in,
                              void* d_out, int out_size)
{
    const int*   x   = (const int*)d_in[0];
    const float* emb = (const float*)d_in[1];
    const float* w1  = (const float*)d_in[2];
    const float* w2  = (const float*)d_in[3];
    const float* w3  = (const float*)d_in[4];
    float* out = (float*)d_out;

    float* pooled; cudaGetSymbolAddress((void**)&pooled, g_pooled);

    cudaFuncSetAttribute(gemm_head,
                         cudaFuncAttributeMaxDynamicSharedMemorySize, SMEM_BYTES);

    pool_and_prep<<<PCTA + TCTA, 256>>>(x, emb, w1, w2);
    gemm_head<<<B / GM, NT, SMEM_BYTES>>>(pooled, w3, out);
}